// round 15
// baseline (speedup 1.0000x reference)
#include <cuda_runtime.h>
#include <cstdint>

#define B_  4
#define S_  1024
#define D_  1024
#define H_  16
#define DK_ 64
#define NX4 ((B_ * S_ * D_) / 4)
#define NW4 ((D_ * D_) / 4)

// Scratch: Q,K pre-rounded tf32 [B,H,S,DK]; V pre-rounded transposed [B,H,DK,S];
// tf32-rounded copies of X and W.
__device__ float g_Q[B_ * H_ * S_ * DK_];
__device__ float g_K[B_ * H_ * S_ * DK_];
__device__ float g_Vt[B_ * H_ * DK_ * S_];
__device__ float g_Xr[3ull * (B_ * S_) * D_];
__device__ float g_Wr[3ull * D_ * D_];

// ---------------------------------------------------------------------------
// Helpers (sm_80-era PTX only: cp.async, ldmatrix, mma.sync tf32)
// ---------------------------------------------------------------------------
__device__ __forceinline__ uint32_t smem_to_u32(const void* p) {
    uint32_t a;
    asm("{ .reg .u64 t; cvta.to.shared.u64 t, %1; cvt.u32.u64 %0, t; }"
        : "=r"(a) : "l"(p));
    return a;
}

#define CP_ASYNC16(dst, src) \
    asm volatile("cp.async.cg.shared.global [%0], [%1], 16;" \
                 :: "r"((uint32_t)(dst)), "l"(src) : "memory")
#define CP_COMMIT() asm volatile("cp.async.commit_group;" ::: "memory")
#define CP_WAIT2()  asm volatile("cp.async.wait_group 2;" ::: "memory")
#define CP_WAIT1()  asm volatile("cp.async.wait_group 1;" ::: "memory")
#define CP_WAIT0()  asm volatile("cp.async.wait_group 0;" ::: "memory")

__device__ __forceinline__ void ldsm4(uint32_t* r, uint32_t addr) {
    asm volatile("ldmatrix.sync.aligned.m8n8.x4.shared.b16 {%0,%1,%2,%3}, [%4];"
                 : "=r"(r[0]), "=r"(r[1]), "=r"(r[2]), "=r"(r[3]) : "r"(addr));
}

__device__ __forceinline__ void mma_tf32(float* c, const uint32_t* a,
                                         uint32_t b0, uint32_t b1) {
    asm volatile(
        "mma.sync.aligned.m16n8k8.row.col.f32.tf32.tf32.f32 "
        "{%0,%1,%2,%3}, {%4,%5,%6,%7}, {%8,%9}, {%0,%1,%2,%3};"
        : "+f"(c[0]), "+f"(c[1]), "+f"(c[2]), "+f"(c[3])
        : "r"(a[0]), "r"(a[1]), "r"(a[2]), "r"(a[3]), "r"(b0), "r"(b1));
}

__device__ __forceinline__ float rtf32(float x) {
    uint32_t r;
    asm("cvt.rna.tf32.f32 %0, %1;" : "=r"(r) : "f"(x));
    return __uint_as_float(r);
}

// ---------------------------------------------------------------------------
// Pre-pass: round fp32 -> tf32 (RNA), all 6 arrays in ONE launch.
// ---------------------------------------------------------------------------
__global__ void tf32_round6(const float4* __restrict__ q,
                            const float4* __restrict__ k,
                            const float4* __restrict__ v,
                            const float4* __restrict__ wq,
                            const float4* __restrict__ wk,
                            const float4* __restrict__ wv,
                            float4* __restrict__ xr,
                            float4* __restrict__ wr) {
    const int y = blockIdx.y;
    const float4* s;
    float4* d;
    int n4;
    if (y < 3) {
        s = (y == 0) ? q : ((y == 1) ? k : v);
        d = xr + (size_t)y * NX4;
        n4 = NX4;
    } else {
        s = (y == 3) ? wq : ((y == 4) ? wk : wv);
        d = wr + (size_t)(y - 3) * NW4;
        n4 = NW4;
    }
    for (int i = blockIdx.x * blockDim.x + threadIdx.x; i < n4;
         i += gridDim.x * blockDim.x) {
        float4 vv = s[i];
        vv.x = rtf32(vv.x); vv.y = rtf32(vv.y);
        vv.z = rtf32(vv.z); vv.w = rtf32(vv.w);
        d[i] = vv;
    }
}

// ---------------------------------------------------------------------------
// tf32 mma.sync projection GEMM, 3-stage cp.async pipeline (2 chunks in
// flight — tests the exposed-L2-latency theory for the 147us proj time).
// Q,K -> RNA-rounded [B,H,S,DK]; V -> RNA-rounded transposed [B,H,DK,S].
// ---------------------------------------------------------------------------
#define PROJ_SMEM (3 * 32768 + 512)

__device__ __forceinline__ void load_chunk(uint32_t stA, uint32_t stB,
                                           const float* __restrict__ X,
                                           const float* __restrict__ W,
                                           int m0, int n0, int k0, int tid) {
#pragma unroll
    for (int i = 0; i < 4; i++) {
        const int q   = tid + i * 256;
        const int row = q >> 3;
        const int c   = q & 7;
        const uint32_t off = (uint32_t)(row * 128) + ((c ^ (row & 7)) << 4);
        CP_ASYNC16(stA + off, X + (size_t)(m0 + row) * D_ + k0 + c * 4);
        CP_ASYNC16(stB + off, W + (size_t)(n0 + row) * D_ + k0 + c * 4);
    }
}

__global__ __launch_bounds__(256, 2)
void proj_mma(const float* __restrict__ bq, const float* __restrict__ bk,
              const float* __restrict__ bv) {
    extern __shared__ char smem[];
    const uint32_t sb = smem_to_u32(smem);

    const int z = blockIdx.z;
    const float* X    = g_Xr + (size_t)z * (B_ * S_) * D_;
    const float* W    = g_Wr + (size_t)z * D_ * D_;
    const float* bias = (z == 0) ? bq : ((z == 1) ? bk : bv);

    const int m0 = blockIdx.y * 128;
    const int n0 = blockIdx.x * 128;
    const int tid = threadIdx.x;
    const int wid = tid >> 5;
    const int lid = tid & 31;
    const int wm = wid >> 2;
    const int wn = wid & 3;

    float* sbias = (float*)(smem + 3 * 32768);
    if (tid < 128) sbias[tid] = bias[n0 + tid];

    const int mrow = lid & 7;
    const int msel = lid >> 3;
    const int aRowHalf   = (msel & 1) * 8;
    const int aChunkHalf = msel >> 1;
    const int bRowHalf   = (msel >> 1) * 8;
    const int bChunkHalf = msel & 1;

    float acc[4][4][4];
#pragma unroll
    for (int i = 0; i < 4; i++)
#pragma unroll
        for (int j = 0; j < 4; j++)
#pragma unroll
            for (int r = 0; r < 4; r++) acc[i][j][r] = 0.f;

    load_chunk(sb,         sb + 16384,         X, W, m0, n0, 0,  tid);
    CP_COMMIT();
    load_chunk(sb + 32768, sb + 32768 + 16384, X, W, m0, n0, 32, tid);
    CP_COMMIT();

    for (int c = 0; c < 32; c++) {
        const uint32_t stA = sb + (uint32_t)(c % 3) * 32768;
        const uint32_t stB = stA + 16384;
        if (c + 2 < 32) {
            const uint32_t nx = sb + (uint32_t)((c + 2) % 3) * 32768;
            load_chunk(nx, nx + 16384, X, W, m0, n0, (c + 2) * 32, tid);
            CP_COMMIT();
            CP_WAIT2();          // chunks c+1, c+2 may be pending; c complete
        } else if (c + 1 < 32) {
            CP_WAIT1();
        } else {
            CP_WAIT0();
        }
        __syncthreads();

#pragma unroll
        for (int ks = 0; ks < 4; ks++) {
            uint32_t a[4][4];
#pragma unroll
            for (int mf = 0; mf < 4; mf++) {
                const int row = wm * 64 + mf * 16 + aRowHalf + mrow;
                ldsm4(a[mf], stA + row * 128 +
                              (((2 * ks + aChunkHalf) ^ mrow) << 4));
            }
            uint32_t bb[2][4];
#pragma unroll
            for (int nf2 = 0; nf2 < 2; nf2++) {
                const int row = wn * 32 + nf2 * 16 + bRowHalf + mrow;
                ldsm4(bb[nf2], stB + row * 128 +
                               (((2 * ks + bChunkHalf) ^ mrow) << 4));
            }
#pragma unroll
            for (int mf = 0; mf < 4; mf++)
#pragma unroll
                for (int nf = 0; nf < 4; nf++)
                    mma_tf32(acc[mf][nf], a[mf],
                             bb[nf >> 1][(nf & 1) * 2],
                             bb[nf >> 1][(nf & 1) * 2 + 1]);
        }
        __syncthreads();
    }

    // Epilogue: bias + RNA-round + scatter.
    const int g = lid >> 2, t = lid & 3;
#pragma unroll
    for (int mf = 0; mf < 4; mf++) {
        const int m = m0 + wm * 64 + mf * 16 + g;
        const int b = m >> 10;
        const int s = m & 1023;
#pragma unroll
        for (int nf = 0; nf < 4; nf++) {
            const int nl = wn * 32 + nf * 8 + 2 * t;
            const int n = n0 + nl;
            const int h = n >> 6;
            const int d = n & 63;
            const float b0v = sbias[nl], b1v = sbias[nl + 1];
            const float v0 = rtf32(acc[mf][nf][0] + b0v);
            const float v1 = rtf32(acc[mf][nf][1] + b1v);
            const float v2 = rtf32(acc[mf][nf][2] + b0v);
            const float v3 = rtf32(acc[mf][nf][3] + b1v);
            if (z == 2) {
                // V: transposed [B,H,DK,S]
                const size_t gb = ((size_t)(b * H_ + h) * DK_ + d) * S_;
                g_Vt[gb + s]          = v0;
                g_Vt[gb + S_ + s]     = v1;
                g_Vt[gb + s + 8]      = v2;
                g_Vt[gb + S_ + s + 8] = v3;
            } else {
                float* out = (z == 0) ? g_Q : g_K;
                const size_t base = (((size_t)(b * H_ + h) * S_) + s) * 64 + d;
                *(float2*)(out + base)          = make_float2(v0, v1);
                *(float2*)(out + base + 8 * 64) = make_float2(v2, v3);
            }
        }
    }
}

// ---------------------------------------------------------------------------
// Flash attention, pure 1xTF32 mma.sync. P transported from the S accumulator
// to the PV A-fragment via register shfl (no smem staging round-trip).
// cp.async double-buffered K/V tiles, warp-local softmax, 2 CTAs/SM,
// persistent mask, masked warp-tiles and masked 16-col blocks skipped.
// ---------------------------------------------------------------------------
// Stage s (s=0,1) at byte offset s*32768: K @ +0, Vt @ +16384.
#define AS_STAGE 32768
#define AS_MSK   65536      // persistent mask: 1024 ints (4KB)
#define ATT_SMEM (65536 + 4096)

__device__ __forceinline__ void att_load(uint32_t stg,
                                         const float* __restrict__ Kg,
                                         const float* __restrict__ Vt,
                                         int kt, int tid) {
#pragma unroll
    for (int i = 0; i < 4; i++) {
        const int e = tid + i * 256;          // 0..1023 16B chunks
        const int r = e >> 4;                 // 0..63
        const int c = (e & 15) * 4;           // 0..60
        const uint32_t off = ((c >> 5) << 13) + r * 128 +
                             ((((c & 31) >> 2) ^ (r & 7)) << 4);
        CP_ASYNC16(stg + off,         Kg + (size_t)(kt + r) * 64 + c);
        CP_ASYNC16(stg + 16384 + off, Vt + (size_t)r * S_ + kt + c);
    }
}

__global__ __launch_bounds__(256, 2)
void attn_mma(const int* __restrict__ amask, float* __restrict__ out) {
    extern __shared__ char smem[];
    const uint32_t sb = smem_to_u32(smem);
    int* msk = (int*)(smem + AS_MSK);

    const int bh = blockIdx.y;
    const int b  = bh >> 4;
    const int h  = bh & 15;
    const int qb = (gridDim.x - 1) - blockIdx.x;   // heavy blocks first
    const int q0 = qb * 128;
    const int tid = threadIdx.x;
    const int wq  = tid >> 5;
    const int lid = tid & 31;
    const int g = lid >> 2, t = lid & 3;

    const int mrow = lid & 7;
    const int msel = lid >> 3;
    const int bRowHalf   = (msel >> 1) * 8;
    const int bChunkHalf = msel & 1;

    const float* Qg  = g_Q  + (size_t)bh * S_ * DK_;
    const float* Kg  = g_K  + (size_t)bh * S_ * DK_;
    const float* Vtg = g_Vt + (size_t)bh * DK_ * S_;

    // ---- persistent mask for this batch row (whole sequence, loaded once)
#pragma unroll
    for (int i = 0; i < 4; i++) msk[tid + i * 256] = amask[b * S_ + tid + i * 256];

    // ---- Q A-fragments (pre-rounded in proj), loaded once.
    uint32_t qh[8][4];
    {
        const float* q0p = Qg + (size_t)(q0 + wq * 16 + g) * 64;
        const float* q8p = q0p + 8 * 64;
#pragma unroll
        for (int ks = 0; ks < 8; ks++) {
            qh[ks][0] = __float_as_uint(q0p[ks * 8 + t]);
            qh[ks][1] = __float_as_uint(q8p[ks * 8 + t]);
            qh[ks][2] = __float_as_uint(q0p[ks * 8 + t + 4]);
            qh[ks][3] = __float_as_uint(q8p[ks * 8 + t + 4]);
        }
    }

    float o[8][4];
    float m0r = -1e30f, m1r = -1e30f, l0r = 0.f, l1r = 0.f;
#pragma unroll
    for (int nf = 0; nf < 8; nf++)
#pragma unroll
        for (int r = 0; r < 4; r++) o[nf][r] = 0.f;

    const int row0 = q0 + wq * 16 + g;
    const int row1 = row0 + 8;
    const int wrow_max = q0 + wq * 16 + 15;   // warp's max q row
    const int ntiles = (qb + 1) * 2;

    att_load(sb, Kg, Vtg, 0, tid);
    CP_COMMIT();

    for (int it = 0; it < ntiles; it++) {
        const int kt = it * 64;
        const uint32_t stg = sb + (it & 1) * AS_STAGE;
        if (it + 1 < ntiles) {
            att_load(sb + ((it + 1) & 1) * AS_STAGE, Kg, Vtg, kt + 64, tid);
            CP_COMMIT();
            CP_WAIT1();
        } else {
            CP_WAIT0();
        }
        __syncthreads();

        // Fully-masked warp-tile (all rows < all cols): provably a no-op on
        // m/l/o — skip all compute, keep the barriers.
        if (wrow_max >= kt) {
            // ---- S = Q K^T  (16-col blocks fully above the diagonal skipped:
            // their mmas only feed lanes that the mask sets to -inf anyway)
            float s[8][4];
#pragma unroll
            for (int nf = 0; nf < 8; nf++)
#pragma unroll
                for (int r = 0; r < 4; r++) s[nf][r] = 0.f;

#pragma unroll
            for (int ks = 0; ks < 8; ks++) {
                const uint32_t coff = ((ks >> 2) << 13) +
                                      (((2 * (ks & 3) + bChunkHalf) ^ mrow) << 4);
#pragma unroll
                for (int nf2 = 0; nf2 < 4; nf2++) {
                    if (kt + nf2 * 16 > wrow_max) continue;   // warp-uniform
                    const int row = nf2 * 16 + bRowHalf + mrow;
                    uint32_t bb[4];
                    ldsm4(bb, stg + row * 128 + coff);
                    mma_tf32(s[nf2 * 2],     qh[ks], bb[0], bb[1]);
                    mma_tf32(s[nf2 * 2 + 1], qh[ks], bb[2], bb[3]);
                }
            }

            // ---- mask + scale (persistent mask)
#pragma unroll
            for (int nf = 0; nf < 8; nf++) {
                const int c0 = nf * 8 + 2 * t;
                const int kg0 = kt + c0, kg1 = kg0 + 1;
                const bool d0 = (msk[kg0] == 0), d1 = (msk[kg1] == 0);
                s[nf][0] = (d0 || kg0 > row0) ? -1e30f : s[nf][0] * 0.125f;
                s[nf][1] = (d1 || kg1 > row0) ? -1e30f : s[nf][1] * 0.125f;
                s[nf][2] = (d0 || kg0 > row1) ? -1e30f : s[nf][2] * 0.125f;
                s[nf][3] = (d1 || kg1 > row1) ? -1e30f : s[nf][3] * 0.125f;
            }

            // ---- online softmax (warp-local over 4 t-lanes)
            float rm0 = -1e30f, rm1 = -1e30f;
#pragma unroll
            for (int nf = 0; nf < 8; nf++) {
                rm0 = fmaxf(rm0, fmaxf(s[nf][0], s[nf][1]));
                rm1 = fmaxf(rm1, fmaxf(s[nf][2], s[nf][3]));
            }
            rm0 = fmaxf(rm0, __shfl_xor_sync(0xffffffffu, rm0, 1));
            rm0 = fmaxf(rm0, __shfl_xor_sync(0xffffffffu, rm0, 2));
            rm1 = fmaxf(rm1, __shfl_xor_sync(0xffffffffu, rm1, 1));
            rm1 = fmaxf(rm1, __shfl_xor_sync(0xffffffffu, rm1, 2));

            const float mn0 = fmaxf(m0r, rm0), mn1 = fmaxf(m1r, rm1);
            const float cr0 = __expf(m0r - mn0), cr1 = __expf(m1r - mn1);
            m0r = mn0; m1r = mn1;

            float rs0 = 0.f, rs1 = 0.f;
#pragma unroll
            for (int nf = 0; nf < 8; nf++) {
                // keep ROUNDED p in the accumulator regs; sum l from the SAME
                // rounded values so the P-rounding bias cancels in O/l.
                float h0 = rtf32(__expf(s[nf][0] - mn0));
                float h1 = rtf32(__expf(s[nf][1] - mn0));
                float h2 = rtf32(__expf(s[nf][2] - mn1));
                float h3 = rtf32(__expf(s[nf][3] - mn1));
                rs0 += h0 + h1;  rs1 += h2 + h3;
                s[nf][0] = h0; s[nf][1] = h1; s[nf][2] = h2; s[nf][3] = h3;
            }
            rs0 += __shfl_xor_sync(0xffffffffu, rs0, 1);
            rs0 += __shfl_xor_sync(0xffffffffu, rs0, 2);
            rs1 += __shfl_xor_sync(0xffffffffu, rs1, 1);
            rs1 += __shfl_xor_sync(0xffffffffu, rs1, 2);
            l0r = l0r * cr0 + rs0;
            l1r = l1r * cr1 + rs1;

#pragma unroll
            for (int nf = 0; nf < 8; nf++) {
                o[nf][0] *= cr0; o[nf][1] *= cr0;
                o[nf][2] *= cr1; o[nf][3] *= cr1;
            }

            // ---- O += P V.  P A-fragment (thread (g,t) needs P[g][ks*8+t],
            // P[g+8][ks*8+t], P[g][ks*8+t+4], P[g+8][ks*8+t+4]) comes from the
            // S accumulator of lane (g, (t or t+4)>>1), slot parity t&1.
            const int srcA = (g << 2) + (t >> 1);
            const bool odd = (t & 1);
#pragma unroll
            for (int ks = 0; ks < 8; ks++) {
                if (kt + ks * 8 > wrow_max) continue;   // zero-A chunk: no-op
                const float b0 = __shfl_sync(0xffffffffu, s[ks][0], srcA);
                const float b1 = __shfl_sync(0xffffffffu, s[ks][1], srcA);
                const float b2 = __shfl_sync(0xffffffffu, s[ks][2], srcA);
                const float b3 = __shfl_sync(0xffffffffu, s[ks][3], srcA);
                const float c0v = __shfl_sync(0xffffffffu, s[ks][0], srcA + 2);
                const float c1v = __shfl_sync(0xffffffffu, s[ks][1], srcA + 2);
                const float c2v = __shfl_sync(0xffffffffu, s[ks][2], srcA + 2);
                const float c3v = __shfl_sync(0xffffffffu, s[ks][3], srcA + 2);
                uint32_t ah[4];
                ah[0] = __float_as_uint(odd ? b1 : b0);
                ah[1] = __float_as_uint(odd ? b3 : b2);
                ah[2] = __float_as_uint(odd ? c1v : c0v);
                ah[3] = __float_as_uint(odd ? c3v : c2v);

                const uint32_t coff = ((ks >> 2) << 13) +
                                      (((2 * (ks & 3) + bChunkHalf) ^ mrow) << 4);
#pragma unroll
                for (int nf2 = 0; nf2 < 4; nf2++) {
                    const int row = nf2 * 16 + bRowHalf + mrow;
                    uint32_t vv[4];
                    ldsm4(vv, stg + 16384 + row * 128 + coff);
                    mma_tf32(o[nf2 * 2],     ah, vv[0], vv[1]);
                    mma_tf32(o[nf2 * 2 + 1], ah, vv[2], vv[3]);
                }
            }
        }
        __syncthreads();   // stage reuse safe for next iteration
    }

    // ---- epilogue: O / l -> out [B, S, H*DK]
    const float i0 = 1.f / l0r, i1 = 1.f / l1r;
    float* o0p = out + ((size_t)b * S_ + row0) * D_ + h * DK_;
    float* o1p = out + ((size_t)b * S_ + row1) * D_ + h * DK_;
#pragma unroll
    for (int nf = 0; nf < 8; nf++) {
        const int d = nf * 8 + 2 * t;
        *(float2*)(o0p + d) = make_float2(o[nf][0] * i0, o[nf][1] * i0);
        *(float2*)(o1p + d) = make_float2(o[nf][2] * i1, o[nf][3] * i1);
    }
}

// ---------------------------------------------------------------------------
// Launch
// ---------------------------------------------------------------------------
extern "C" void kernel_launch(void* const* d_in, const int* in_sizes, int n_in,
                              void* d_out, int out_size) {
    const float* query = (const float*)d_in[0];
    const float* key   = (const float*)d_in[1];
    const float* value = (const float*)d_in[2];
    const int*   amask = (const int*)d_in[3];
    const float* Wq    = (const float*)d_in[4];
    const float* bq    = (const float*)d_in[5];
    const float* Wk    = (const float*)d_in[6];
    const float* bk    = (const float*)d_in[7];
    const float* Wv    = (const float*)d_in[8];
    const float* bv    = (const float*)d_in[9];
    float* out = (float*)d_out;

    float* xr;  cudaGetSymbolAddress((void**)&xr, g_Xr);
    float* wr;  cudaGetSymbolAddress((void**)&wr, g_Wr);

    tf32_round6<<<dim3(256, 6), 256>>>(
        (const float4*)query, (const float4*)key, (const float4*)value,
        (const float4*)Wq, (const float4*)Wk, (const float4*)Wv,
        (float4*)xr, (float4*)wr);

    cudaFuncSetAttribute(proj_mma, cudaFuncAttributeMaxDynamicSharedMemorySize,
                         PROJ_SMEM);
    proj_mma<<<dim3(8, 32, 3), 256, PROJ_SMEM>>>(bq, bk, bv);

    cudaFuncSetAttribute(attn_mma, cudaFuncAttributeMaxDynamicSharedMemorySize,
                         ATT_SMEM);
    attn_mma<<<dim3(S_ / 128, B_ * H_), 256, ATT_SMEM>>>(amask, out);
}